// round 12
// baseline (speedup 1.0000x reference)
#include <cuda_runtime.h>
#include <cuda_fp16.h>
#include <cstdint>

// ---------------- problem constants ----------------
#define M_ROWS   8192          // 4 * 2048
#define K_IN     4096
#define N_OUT    4096
#define N_OUTL   40
#define XO_COLS  64            // padded outlier column block
#define K_EXT    (K_IN + XO_COLS)   // 4160: [W_fp16 | B_outlier]

// ---------------- device scratch (static, no allocation) ----------------
__device__ unsigned       g_absmax_bits;
__device__ unsigned char  g_mask[K_IN];
__device__ short          g_ord[K_IN];
__device__ __half         g_q  [(size_t)M_ROWS * K_IN];     // 64 MB, q ints as fp16 (exact)
__device__ __half         g_xo [(size_t)M_ROWS * XO_COLS];  // 1 MB, (x - x_clip)/scale
__device__ __half         g_w2 [(size_t)N_OUT * K_EXT];     // 34 MB: [W | B | 0-pad]

// ---------------- fused init: mask/ord/absmax reset + zero g_xo ----------------
__global__ void init_kernel(const int* __restrict__ idx) {
    int b = blockIdx.x, t = threadIdx.x;
    int i = b * blockDim.x + t;                    // 1024*256 threads: zero g_xo
    reinterpret_cast<unsigned*>(g_xo)[i] = 0u;
    if (b == 0) {
        for (int c = t; c < K_IN; c += blockDim.x) { g_mask[c] = 1; g_ord[c] = -1; }
        __syncthreads();
        if (t < N_OUTL) { int c = idx[t]; g_mask[c] = 0; g_ord[c] = (short)t; }
        if (t == 0) g_absmax_bits = 0u;
    }
}

// ---------------- masked abs-max (standalone: wconv moved to quant phase) ----------------
__global__ void absmax_kernel(const float4* __restrict__ x, int n4) {
    float m = 0.f;
    int stride = gridDim.x * blockDim.x;
    int i = blockIdx.x * blockDim.x + threadIdx.x;
    for (; i + stride < n4; i += 2 * stride) {
        float4 v0 = x[i];
        float4 v1 = x[i + stride];
        int c0 = (i << 2) & (K_IN - 1);
        int c1 = ((i + stride) << 2) & (K_IN - 1);
        float a0 = g_mask[c0 + 0] ? fabsf(v0.x) : 0.f;
        float a1 = g_mask[c0 + 1] ? fabsf(v0.y) : 0.f;
        float a2 = g_mask[c0 + 2] ? fabsf(v0.z) : 0.f;
        float a3 = g_mask[c0 + 3] ? fabsf(v0.w) : 0.f;
        float b0 = g_mask[c1 + 0] ? fabsf(v1.x) : 0.f;
        float b1 = g_mask[c1 + 1] ? fabsf(v1.y) : 0.f;
        float b2 = g_mask[c1 + 2] ? fabsf(v1.z) : 0.f;
        float b3 = g_mask[c1 + 3] ? fabsf(v1.w) : 0.f;
        m = fmaxf(m, fmaxf(fmaxf(fmaxf(a0, a1), fmaxf(a2, a3)),
                           fmaxf(fmaxf(b0, b1), fmaxf(b2, b3))));
    }
    if (i < n4) {
        float4 v = x[i];
        int col = (i << 2) & (K_IN - 1);
        float a0 = g_mask[col + 0] ? fabsf(v.x) : 0.f;
        float a1 = g_mask[col + 1] ? fabsf(v.y) : 0.f;
        float a2 = g_mask[col + 2] ? fabsf(v.z) : 0.f;
        float a3 = g_mask[col + 3] ? fabsf(v.w) : 0.f;
        m = fmaxf(m, fmaxf(fmaxf(a0, a1), fmaxf(a2, a3)));
    }
    #pragma unroll
    for (int o = 16; o; o >>= 1) m = fmaxf(m, __shfl_xor_sync(0xffffffffu, m, o));
    __shared__ float sm[8];
    if ((threadIdx.x & 31) == 0) sm[threadIdx.x >> 5] = m;
    __syncthreads();
    if (threadIdx.x < 8) {
        m = sm[threadIdx.x];
        #pragma unroll
        for (int o = 4; o; o >>= 1) m = fmaxf(m, __shfl_xor_sync(0xffu, m, o));
        if (threadIdx.x == 0) atomicMax(&g_absmax_bits, __float_as_uint(m));
    }
}

// ---------------- fused: quantize (blocks 0..2047) + weight convert (2048..3071) ----------------
#define QT_BLOCKS 2048
#define WC_BLOCKS 1024
#define WCHUNKS   (N_OUT * (K_EXT / 8))   // 4096 * 520 chunks

__global__ void quant_wconv_kernel(const float4* __restrict__ x,
                                   const float* __restrict__ W,
                                   const float* __restrict__ Bm) {
    if (blockIdx.x < QT_BLOCKS) {
        const float upper = __uint_as_float(g_absmax_bits);
        const float inv = 127.0f / fmaxf(upper, 1e-5f);
        const int n8 = M_ROWS * K_IN / 8;
        int stride = QT_BLOCKS * blockDim.x;
        for (int i = blockIdx.x * blockDim.x + threadIdx.x; i < n8; i += stride) {
            float4 v0 = x[2 * i];
            float4 v1 = x[2 * i + 1];
            int e   = i << 3;
            int row = e >> 12;
            int col = e & (K_IN - 1);
            float xc[8];
            xc[0] = fminf(fmaxf(v0.x, -upper), upper);
            xc[1] = fminf(fmaxf(v0.y, -upper), upper);
            xc[2] = fminf(fmaxf(v0.z, -upper), upper);
            xc[3] = fminf(fmaxf(v0.w, -upper), upper);
            xc[4] = fminf(fmaxf(v1.x, -upper), upper);
            xc[5] = fminf(fmaxf(v1.y, -upper), upper);
            xc[6] = fminf(fmaxf(v1.z, -upper), upper);
            xc[7] = fminf(fmaxf(v1.w, -upper), upper);
            __half h[8];
            #pragma unroll
            for (int jj = 0; jj < 8; ++jj) h[jj] = __float2half_rn(rintf(xc[jj] * inv));
            *reinterpret_cast<uint4*>(g_q + e) = *reinterpret_cast<uint4*>(h);
            float vv[8] = {v0.x, v0.y, v0.z, v0.w, v1.x, v1.y, v1.z, v1.w};
            #pragma unroll
            for (int jj = 0; jj < 8; ++jj) {
                int o = g_ord[col + jj];
                if (o >= 0)
                    g_xo[(size_t)row * XO_COLS + o] = __float2half_rn((vv[jj] - xc[jj]) * inv);
            }
        }
    } else {
        int stride = WC_BLOCKS * blockDim.x;
        for (int c = (blockIdx.x - QT_BLOCKS) * blockDim.x + threadIdx.x;
             c < WCHUNKS; c += stride) {
            int n  = c / (K_EXT / 8);
            int k8 = c - n * (K_EXT / 8);
            int k0 = k8 * 8;
            __half h[8];
            if (k0 < K_IN) {
                const float* src = W + (size_t)n * K_IN + k0;
                float4 f0 = *reinterpret_cast<const float4*>(src);
                float4 f1 = *reinterpret_cast<const float4*>(src + 4);
                h[0] = __float2half_rn(f0.x); h[1] = __float2half_rn(f0.y);
                h[2] = __float2half_rn(f0.z); h[3] = __float2half_rn(f0.w);
                h[4] = __float2half_rn(f1.x); h[5] = __float2half_rn(f1.y);
                h[6] = __float2half_rn(f1.z); h[7] = __float2half_rn(f1.w);
            } else {
                int j0 = k0 - K_IN;
                #pragma unroll
                for (int jj = 0; jj < 8; ++jj) {
                    int j = j0 + jj;
                    float v = (j < N_OUTL) ? Bm[(size_t)n * N_OUTL + j] : 0.0f;
                    h[jj] = __float2half_rn(v);
                }
            }
            *reinterpret_cast<uint4*>(g_w2 + (size_t)n * K_EXT + k0) =
                *reinterpret_cast<uint4*>(h);
        }
    }
}

// ---------------- main GEMM: M=8192, N=4096, K=4160 (fp16 mma.sync) ----------------
// CTA 128x128, 4 warps 2x2, warp tile 64x64, 2 CTAs/SM. Rotated loop:
// [ldmatrix -> MMAs with cp.async issues INTERLEAVED -> wait3 -> barrier].
// The interleave breaks the per-iteration LSU burst (8 LDGSTS + 16 LDSM
// back-to-back) that was draining the tensor pipe ~25% of each iteration.
#define BM 128
#define BN 128
#define BK 32
#define NTHREADS 128
#define STAGES 5
#define ROWB 80                          // padded row: 32 fp16 = 64B data + 16B pad
#define TILEB (128 * ROWB)               // 10240 B per operand tile per stage
#define SMEM_BYTES (STAGES * TILEB * 2)  // 102400 B

__device__ __forceinline__ void cp16(unsigned dst, const void* src) {
    asm volatile("cp.async.cg.shared.global [%0], [%1], 16;\n" :: "r"(dst), "l"(src));
}
__device__ __forceinline__ void cp_commit() { asm volatile("cp.async.commit_group;\n" ::: "memory"); }
__device__ __forceinline__ void cp_wait3()  { asm volatile("cp.async.wait_group 3;\n" ::: "memory"); }

__device__ __forceinline__ void ldm_x4(unsigned addr, unsigned& r0, unsigned& r1,
                                       unsigned& r2, unsigned& r3) {
    asm volatile("ldmatrix.sync.aligned.m8n8.x4.shared.b16 {%0,%1,%2,%3}, [%4];\n"
                 : "=r"(r0), "=r"(r1), "=r"(r2), "=r"(r3) : "r"(addr));
}
__device__ __forceinline__ void mma_f16(float* d, const unsigned* a, const unsigned* b) {
    asm volatile("mma.sync.aligned.m16n8k16.row.col.f32.f16.f16.f32 "
                 "{%0,%1,%2,%3},{%4,%5,%6,%7},{%8,%9},{%0,%1,%2,%3};\n"
                 : "+f"(d[0]), "+f"(d[1]), "+f"(d[2]), "+f"(d[3])
                 : "r"(a[0]), "r"(a[1]), "r"(a[2]), "r"(a[3]), "r"(b[0]), "r"(b[1]));
}

// one of the 8 load chunks of a stage (c = 0..7; even: A, odd: B)
__device__ __forceinline__ void load_chunk(int c, int stage, int k0, int m0, int n0,
                                           int tid, unsigned sA, unsigned sB) {
    int half = c >> 1;                       // 0..3
    int idx = tid + half * NTHREADS;
    int row = idx >> 2;
    int ch  = idx & 3;
    if ((c & 1) == 0) {
        const __half* srcA;
        if (k0 < K_IN)
            srcA = g_q  + (size_t)(m0 + row) * K_IN + (k0 + ch * 8);
        else
            srcA = g_xo + (size_t)(m0 + row) * XO_COLS + (k0 - K_IN) + ch * 8;
        cp16(sA + stage * TILEB + row * ROWB + ch * 16, srcA);
    } else {
        const __half* srcB = g_w2 + (size_t)(n0 + row) * K_EXT + k0 + ch * 8;
        cp16(sB + stage * TILEB + row * ROWB + ch * 16, srcB);
    }
}

__device__ __forceinline__ void load_stage(int stage, int k0, int m0, int n0, int tid,
                                           unsigned sA, unsigned sB) {
    #pragma unroll
    for (int c = 0; c < 8; ++c) load_chunk(c, stage, k0, m0, n0, tid, sA, sB);
}

__global__ void __launch_bounds__(NTHREADS, 2)
gemm_kernel(const float* __restrict__ bias, float* __restrict__ out) {
    extern __shared__ unsigned char smem[];
    unsigned sbase = (unsigned)__cvta_generic_to_shared(smem);
    unsigned sA = sbase;
    unsigned sB = sbase + STAGES * TILEB;

    const int tid  = threadIdx.x;
    const int lane = tid & 31;
    const int warp = tid >> 5;
    const int wm   = warp & 1;    // 2 warps along M: 64 rows each
    const int wn   = warp >> 1;   // 2 warps along N: 64 cols each
    const int m0   = blockIdx.y * BM;
    const int n0   = blockIdx.x * BN;

    float acc[4][8][4];
    #pragma unroll
    for (int i = 0; i < 4; ++i)
        #pragma unroll
        for (int j = 0; j < 8; ++j)
            #pragma unroll
            for (int k = 0; k < 4; ++k) acc[i][j][k] = 0.f;

    const int NIT = K_EXT / BK;   // 130
    // prologue: stages 0..3 (groups == stages), then publish stage 0
    load_stage(0, 0 * BK, m0, n0, tid, sA, sB); cp_commit();
    load_stage(1, 1 * BK, m0, n0, tid, sA, sB); cp_commit();
    load_stage(2, 2 * BK, m0, n0, tid, sA, sB); cp_commit();
    load_stage(3, 3 * BK, m0, n0, tid, sA, sB); cp_commit();
    cp_wait3();          // stage 0 complete (per-thread)
    __syncthreads();     // stage 0 published to all threads

    // ldmatrix per-lane address components
    const int arow  = (lane & 7) + ((lane >> 3) & 1) * 8;
    const int acolb = ((lane >> 4) & 1) * 16;
    const int brow  = (lane & 7) + ((lane >> 4) & 1) * 8;
    const int bcolb = ((lane >> 3) & 1) * 16;
    const unsigned aBase = sA + (unsigned)(wm * 64 + arow) * ROWB + acolb;
    const unsigned bBase = sB + (unsigned)(wn * 64 + brow) * ROWB + bcolb;

    for (int it = 0; it < NIT; ++it) {
        // INVARIANT at loop top: stage it resident in all threads and
        // published (prologue barrier for it=0; end-of-iter barrier for it>0,
        // which followed wait3 covering stages <= it).
        int st = it % STAGES;
        unsigned aSt = aBase + st * TILEB;
        unsigned bSt = bBase + st * TILEB;
        unsigned a[2][4][4], b[2][8][2];
        #pragma unroll
        for (int ks = 0; ks < 2; ++ks) {
            #pragma unroll
            for (int mf = 0; mf < 4; ++mf)
                ldm_x4(aSt + mf * 16 * ROWB + ks * 32,
                       a[ks][mf][0], a[ks][mf][1], a[ks][mf][2], a[ks][mf][3]);
            #pragma unroll
            for (int p = 0; p < 4; ++p) {
                unsigned r0, r1, r2, r3;
                ldm_x4(bSt + p * 16 * ROWB + ks * 32, r0, r1, r2, r3);
                b[ks][2 * p][0] = r0;     b[ks][2 * p][1] = r1;
                b[ks][2 * p + 1][0] = r2; b[ks][2 * p + 1][1] = r3;
            }
        }
        // MMAs with the next stage's 8 cp.asyncs interleaved (1 per 8 MMAs).
        // Target slot (it+4)%5 == (it-1)%5: its reads finished at iter it-1,
        // published by the end-of-iter-(it-1) barrier.
        int nk = it + STAGES - 1;
        bool doload = (nk < NIT);
        int kload = nk * BK;
        int sload = nk % STAGES;
        #pragma unroll
        for (int ks = 0; ks < 2; ++ks)
            #pragma unroll
            for (int mf = 0; mf < 4; ++mf) {
                if (doload) load_chunk(ks * 4 + mf, sload, kload, m0, n0, tid, sA, sB);
                #pragma unroll
                for (int nf = 0; nf < 8; ++nf)
                    mma_f16(acc[mf][nf], a[ks][mf], b[ks][nf]);
            }
        cp_commit();     // group == stage it+4 (empty group near tail: fine)
        // wait: groups <= it+1 complete (last committed = it+4, pending <= 3)
        cp_wait3();
        // barrier: publishes stages <= it+1 for next iter's ldmatrix AND
        // frees slot it%5 (this iter's reads are done) for iter it+1's loads.
        __syncthreads();
    }

    // epilogue: out = scale*acc + bias
    const float upper = __uint_as_float(g_absmax_bits);
    const float s = fmaxf(upper, 1e-5f) * (1.0f / 127.0f);
    const int gr = lane >> 2, tc = lane & 3;
    #pragma unroll
    for (int mf = 0; mf < 4; ++mf) {
        int r0 = m0 + wm * 64 + mf * 16 + gr;
        #pragma unroll
        for (int nf = 0; nf < 8; ++nf) {
            int cc = n0 + wn * 64 + nf * 8 + tc * 2;
            float2 bv = *reinterpret_cast<const float2*>(bias + cc);
            float2 o0, o1;
            o0.x = acc[mf][nf][0] * s + bv.x;  o0.y = acc[mf][nf][1] * s + bv.y;
            o1.x = acc[mf][nf][2] * s + bv.x;  o1.y = acc[mf][nf][3] * s + bv.y;
            *reinterpret_cast<float2*>(out + (size_t)r0 * N_OUT + cc)       = o0;
            *reinterpret_cast<float2*>(out + (size_t)(r0 + 8) * N_OUT + cc) = o1;
        }
    }
}

// ---------------- launch ----------------
extern "C" void kernel_launch(void* const* d_in, const int* in_sizes, int n_in,
                              void* d_out, int out_size) {
    const float* x    = (const float*)d_in[0];   // [4,2048,4096]
    const float* W    = (const float*)d_in[1];   // [4096,4096]
    const float* Bm   = (const float*)d_in[2];   // [4096,40]
    const float* bias = (const float*)d_in[3];   // [1,4096]
    const int*   idx  = (const int*)  d_in[4];   // [40]
    float* out = (float*)d_out;
    (void)in_sizes; (void)n_in; (void)out_size;

    init_kernel<<<1024, 256>>>(idx);
    absmax_kernel<<<2048, 256>>>((const float4*)x, M_ROWS * K_IN / 4);
    quant_wconv_kernel<<<QT_BLOCKS + WC_BLOCKS, 256>>>((const float4*)x, W, Bm);

    cudaFuncSetAttribute(gemm_kernel, cudaFuncAttributeMaxDynamicSharedMemorySize, SMEM_BYTES);
    dim3 grid(N_OUT / BN, M_ROWS / BM);   // n fastest: CTAs sharing an A strip co-run
    gemm_kernel<<<grid, NTHREADS, SMEM_BYTES>>>(bias, out);
}

// round 13
// speedup vs baseline: 1.2756x; 1.2756x over previous
#include <cuda_runtime.h>
#include <cuda_fp16.h>
#include <cstdint>

// ---------------- problem constants ----------------
#define M_ROWS   8192          // 4 * 2048
#define K_IN     4096
#define N_OUT    4096
#define N_OUTL   40
#define XO_COLS  64            // padded outlier column block
#define K_EXT    (K_IN + XO_COLS)   // 4160: [W_fp16 | B_outlier]

// ---------------- device scratch (static, no allocation) ----------------
__device__ unsigned       g_absmax_bits;
__device__ unsigned char  g_mask[K_IN];
__device__ short          g_ord[K_IN];
__device__ __half         g_q  [(size_t)M_ROWS * K_IN];     // 64 MB, q ints as fp16 (exact)
__device__ __half         g_xo [(size_t)M_ROWS * XO_COLS];  // 1 MB, (x - x_clip)/scale
__device__ __half         g_w2 [(size_t)N_OUT * K_EXT];     // 34 MB: [W | B | 0-pad]

// ---------------- init: mask / ordinal map / absmax reset (1 block) ----------------
__global__ void init_kernel(const int* __restrict__ idx) {
    int t = threadIdx.x;
    for (int c = t; c < K_IN; c += blockDim.x) { g_mask[c] = 1; g_ord[c] = -1; }
    __syncthreads();
    if (t < N_OUTL) { int c = idx[t]; g_mask[c] = 0; g_ord[c] = (short)t; }
    if (t == 0) g_absmax_bits = 0u;
}

// ---------------- fused: masked abs-max (blocks 0..2047) + weight convert (2048..3071) ----------------
#define AM_BLOCKS 2048
#define WC_BLOCKS 1024
#define WCHUNKS   (N_OUT * (K_EXT / 8))   // 4096 * 520 chunks

__global__ void absmax_wconv_kernel(const float4* __restrict__ x, int n4,
                                    const float* __restrict__ W,
                                    const float* __restrict__ Bm) {
    if (blockIdx.x < AM_BLOCKS) {
        float m = 0.f;
        int stride = AM_BLOCKS * blockDim.x;
        int i = blockIdx.x * blockDim.x + threadIdx.x;
        for (; i + stride < n4; i += 2 * stride) {
            float4 v0 = x[i];
            float4 v1 = x[i + stride];
            int c0 = (i << 2) & (K_IN - 1);
            int c1 = ((i + stride) << 2) & (K_IN - 1);
            float a0 = g_mask[c0 + 0] ? fabsf(v0.x) : 0.f;
            float a1 = g_mask[c0 + 1] ? fabsf(v0.y) : 0.f;
            float a2 = g_mask[c0 + 2] ? fabsf(v0.z) : 0.f;
            float a3 = g_mask[c0 + 3] ? fabsf(v0.w) : 0.f;
            float b0 = g_mask[c1 + 0] ? fabsf(v1.x) : 0.f;
            float b1 = g_mask[c1 + 1] ? fabsf(v1.y) : 0.f;
            float b2 = g_mask[c1 + 2] ? fabsf(v1.z) : 0.f;
            float b3 = g_mask[c1 + 3] ? fabsf(v1.w) : 0.f;
            m = fmaxf(m, fmaxf(fmaxf(fmaxf(a0, a1), fmaxf(a2, a3)),
                               fmaxf(fmaxf(b0, b1), fmaxf(b2, b3))));
        }
        if (i < n4) {
            float4 v = x[i];
            int col = (i << 2) & (K_IN - 1);
            float a0 = g_mask[col + 0] ? fabsf(v.x) : 0.f;
            float a1 = g_mask[col + 1] ? fabsf(v.y) : 0.f;
            float a2 = g_mask[col + 2] ? fabsf(v.z) : 0.f;
            float a3 = g_mask[col + 3] ? fabsf(v.w) : 0.f;
            m = fmaxf(m, fmaxf(fmaxf(a0, a1), fmaxf(a2, a3)));
        }
        #pragma unroll
        for (int o = 16; o; o >>= 1) m = fmaxf(m, __shfl_xor_sync(0xffffffffu, m, o));
        __shared__ float sm[8];
        if ((threadIdx.x & 31) == 0) sm[threadIdx.x >> 5] = m;
        __syncthreads();
        if (threadIdx.x < 8) {
            m = sm[threadIdx.x];
            #pragma unroll
            for (int o = 4; o; o >>= 1) m = fmaxf(m, __shfl_xor_sync(0xffu, m, o));
            if (threadIdx.x == 0) atomicMax(&g_absmax_bits, __float_as_uint(m));
        }
    } else {
        int stride = WC_BLOCKS * blockDim.x;
        for (int c = (blockIdx.x - AM_BLOCKS) * blockDim.x + threadIdx.x;
             c < WCHUNKS; c += stride) {
            int n  = c / (K_EXT / 8);
            int k8 = c - n * (K_EXT / 8);
            int k0 = k8 * 8;
            __half h[8];
            if (k0 < K_IN) {
                const float* src = W + (size_t)n * K_IN + k0;
                float4 f0 = *reinterpret_cast<const float4*>(src);
                float4 f1 = *reinterpret_cast<const float4*>(src + 4);
                h[0] = __float2half_rn(f0.x); h[1] = __float2half_rn(f0.y);
                h[2] = __float2half_rn(f0.z); h[3] = __float2half_rn(f0.w);
                h[4] = __float2half_rn(f1.x); h[5] = __float2half_rn(f1.y);
                h[6] = __float2half_rn(f1.z); h[7] = __float2half_rn(f1.w);
            } else {
                int j0 = k0 - K_IN;
                #pragma unroll
                for (int jj = 0; jj < 8; ++jj) {
                    int j = j0 + jj;
                    float v = (j < N_OUTL) ? Bm[(size_t)n * N_OUTL + j] : 0.0f;
                    h[jj] = __float2half_rn(v);
                }
            }
            *reinterpret_cast<uint4*>(g_w2 + (size_t)n * K_EXT + k0) =
                *reinterpret_cast<uint4*>(h);
        }
    }
}

// ---------------- quantize + outlier residual + xo-padding zero ----------------
__global__ void quant_kernel(const float4* __restrict__ x) {
    const float upper = __uint_as_float(g_absmax_bits);
    const float inv = 127.0f / fmaxf(upper, 1e-5f);
    const int n8 = M_ROWS * K_IN / 8;
    int stride = gridDim.x * blockDim.x;
    for (int i = blockIdx.x * blockDim.x + threadIdx.x; i < n8; i += stride) {
        float4 v0 = x[2 * i];
        float4 v1 = x[2 * i + 1];
        int e   = i << 3;
        int row = e >> 12;
        int col = e & (K_IN - 1);
        float xc[8];
        xc[0] = fminf(fmaxf(v0.x, -upper), upper);
        xc[1] = fminf(fmaxf(v0.y, -upper), upper);
        xc[2] = fminf(fmaxf(v0.z, -upper), upper);
        xc[3] = fminf(fmaxf(v0.w, -upper), upper);
        xc[4] = fminf(fmaxf(v1.x, -upper), upper);
        xc[5] = fminf(fmaxf(v1.y, -upper), upper);
        xc[6] = fminf(fmaxf(v1.z, -upper), upper);
        xc[7] = fminf(fmaxf(v1.w, -upper), upper);
        __half h[8];
        #pragma unroll
        for (int jj = 0; jj < 8; ++jj) h[jj] = __float2half_rn(rintf(xc[jj] * inv));
        *reinterpret_cast<uint4*>(g_q + e) = *reinterpret_cast<uint4*>(h);
        float vv[8] = {v0.x, v0.y, v0.z, v0.w, v1.x, v1.y, v1.z, v1.w};
        #pragma unroll
        for (int jj = 0; jj < 8; ++jj) {
            int o = g_ord[col + jj];
            if (o >= 0)
                g_xo[(size_t)row * XO_COLS + o] = __float2half_rn((vv[jj] - xc[jj]) * inv);
        }
        // each row's first chunk also zeroes xo padding cols 40..63
        if (col == 0) {
            uint4 z = make_uint4(0, 0, 0, 0);
            uint4* pad = reinterpret_cast<uint4*>(g_xo + (size_t)row * XO_COLS + 40);
            pad[0] = z; pad[1] = z; pad[2] = z;   // 24 halves = 48 B
        }
    }
}

// ---------------- main GEMM: M=8192, N=4096, K=4160 (fp16 mma.sync) ----------------
// ROUND-9 CHAMPION, UNCHANGED: CTA 128x128, 4 warps 2x2, warp tile 64x64,
// 5-stage cp.async ring, 2 CTAs/SM, fragments pre-hoisted.
#define BM 128
#define BN 128
#define BK 32
#define NTHREADS 128
#define STAGES 5
#define ROWB 80                          // padded row: 32 fp16 = 64B data + 16B pad
#define TILEB (128 * ROWB)               // 10240 B per operand tile per stage
#define SMEM_BYTES (STAGES * TILEB * 2)  // 102400 B

__device__ __forceinline__ void cp16(unsigned dst, const void* src) {
    asm volatile("cp.async.cg.shared.global [%0], [%1], 16;\n" :: "r"(dst), "l"(src));
}
__device__ __forceinline__ void cp_commit() { asm volatile("cp.async.commit_group;\n" ::: "memory"); }
__device__ __forceinline__ void cp_wait3()  { asm volatile("cp.async.wait_group 3;\n" ::: "memory"); }

__device__ __forceinline__ void ldm_x4(unsigned addr, unsigned& r0, unsigned& r1,
                                       unsigned& r2, unsigned& r3) {
    asm volatile("ldmatrix.sync.aligned.m8n8.x4.shared.b16 {%0,%1,%2,%3}, [%4];\n"
                 : "=r"(r0), "=r"(r1), "=r"(r2), "=r"(r3) : "r"(addr));
}
__device__ __forceinline__ void mma_f16(float* d, const unsigned* a, const unsigned* b) {
    asm volatile("mma.sync.aligned.m16n8k16.row.col.f32.f16.f16.f32 "
                 "{%0,%1,%2,%3},{%4,%5,%6,%7},{%8,%9},{%0,%1,%2,%3};\n"
                 : "+f"(d[0]), "+f"(d[1]), "+f"(d[2]), "+f"(d[3])
                 : "r"(a[0]), "r"(a[1]), "r"(a[2]), "r"(a[3]), "r"(b[0]), "r"(b[1]));
}

// stage loader: A 512 16B-chunks + B 512 16B-chunks, 128 threads -> 4+4 per thread
__device__ __forceinline__ void load_stage(int stage, int k0, int m0, int n0, int tid,
                                           unsigned sA, unsigned sB) {
    #pragma unroll
    for (int c = 0; c < 4; ++c) {
        int idx = tid + c * NTHREADS;
        int row = idx >> 2;
        int ch  = idx & 3;
        const __half* srcA;
        if (k0 < K_IN)
            srcA = g_q  + (size_t)(m0 + row) * K_IN + (k0 + ch * 8);
        else
            srcA = g_xo + (size_t)(m0 + row) * XO_COLS + (k0 - K_IN) + ch * 8;
        cp16(sA + stage * TILEB + row * ROWB + ch * 16, srcA);
        const __half* srcB = g_w2 + (size_t)(n0 + row) * K_EXT + k0 + ch * 8;
        cp16(sB + stage * TILEB + row * ROWB + ch * 16, srcB);
    }
}

__global__ void __launch_bounds__(NTHREADS, 2)
gemm_kernel(const float* __restrict__ bias, float* __restrict__ out) {
    extern __shared__ unsigned char smem[];
    unsigned sbase = (unsigned)__cvta_generic_to_shared(smem);
    unsigned sA = sbase;
    unsigned sB = sbase + STAGES * TILEB;

    const int tid  = threadIdx.x;
    const int lane = tid & 31;
    const int warp = tid >> 5;
    const int wm   = warp & 1;    // 2 warps along M: 64 rows each
    const int wn   = warp >> 1;   // 2 warps along N: 64 cols each
    const int m0   = blockIdx.y * BM;
    const int n0   = blockIdx.x * BN;

    float acc[4][8][4];
    #pragma unroll
    for (int i = 0; i < 4; ++i)
        #pragma unroll
        for (int j = 0; j < 8; ++j)
            #pragma unroll
            for (int k = 0; k < 4; ++k) acc[i][j][k] = 0.f;

    const int NIT = K_EXT / BK;   // 130
    load_stage(0, 0 * BK, m0, n0, tid, sA, sB); cp_commit();
    load_stage(1, 1 * BK, m0, n0, tid, sA, sB); cp_commit();
    load_stage(2, 2 * BK, m0, n0, tid, sA, sB); cp_commit();
    load_stage(3, 3 * BK, m0, n0, tid, sA, sB); cp_commit();

    // ldmatrix per-lane address components
    const int arow  = (lane & 7) + ((lane >> 3) & 1) * 8;
    const int acolb = ((lane >> 4) & 1) * 16;
    const int brow  = (lane & 7) + ((lane >> 4) & 1) * 8;
    const int bcolb = ((lane >> 3) & 1) * 16;
    const unsigned aBase = sA + (unsigned)(wm * 64 + arow) * ROWB + acolb;
    const unsigned bBase = sB + (unsigned)(wn * 64 + brow) * ROWB + bcolb;

    for (int it = 0; it < NIT; ++it) {
        cp_wait3();
        __syncthreads();
        int nk = it + STAGES - 1;
        if (nk < NIT) load_stage(nk % STAGES, nk * BK, m0, n0, tid, sA, sB);
        cp_commit();

        int st = it % STAGES;
        unsigned aSt = aBase + st * TILEB;
        unsigned bSt = bBase + st * TILEB;

        unsigned a[2][4][4], b[2][8][2];
        #pragma unroll
        for (int ks = 0; ks < 2; ++ks) {
            #pragma unroll
            for (int mf = 0; mf < 4; ++mf)
                ldm_x4(aSt + mf * 16 * ROWB + ks * 32,
                       a[ks][mf][0], a[ks][mf][1], a[ks][mf][2], a[ks][mf][3]);
            #pragma unroll
            for (int p = 0; p < 4; ++p) {
                unsigned r0, r1, r2, r3;
                ldm_x4(bSt + p * 16 * ROWB + ks * 32, r0, r1, r2, r3);
                b[ks][2 * p][0] = r0;     b[ks][2 * p][1] = r1;
                b[ks][2 * p + 1][0] = r2; b[ks][2 * p + 1][1] = r3;
            }
        }
        #pragma unroll
        for (int ks = 0; ks < 2; ++ks)
            #pragma unroll
            for (int mf = 0; mf < 4; ++mf)
                #pragma unroll
                for (int nf = 0; nf < 8; ++nf)
                    mma_f16(acc[mf][nf], a[ks][mf], b[ks][nf]);
    }

    // epilogue: out = scale*acc + bias
    const float upper = __uint_as_float(g_absmax_bits);
    const float s = fmaxf(upper, 1e-5f) * (1.0f / 127.0f);
    const int gr = lane >> 2, tc = lane & 3;
    #pragma unroll
    for (int mf = 0; mf < 4; ++mf) {
        int r0 = m0 + wm * 64 + mf * 16 + gr;
        #pragma unroll
        for (int nf = 0; nf < 8; ++nf) {
            int cc = n0 + wn * 64 + nf * 8 + tc * 2;
            float2 bv = *reinterpret_cast<const float2*>(bias + cc);
            float2 o0, o1;
            o0.x = acc[mf][nf][0] * s + bv.x;  o0.y = acc[mf][nf][1] * s + bv.y;
            o1.x = acc[mf][nf][2] * s + bv.x;  o1.y = acc[mf][nf][3] * s + bv.y;
            *reinterpret_cast<float2*>(out + (size_t)r0 * N_OUT + cc)       = o0;
            *reinterpret_cast<float2*>(out + (size_t)(r0 + 8) * N_OUT + cc) = o1;
        }
    }
}

// ---------------- launch ----------------
extern "C" void kernel_launch(void* const* d_in, const int* in_sizes, int n_in,
                              void* d_out, int out_size) {
    const float* x    = (const float*)d_in[0];   // [4,2048,4096]
    const float* W    = (const float*)d_in[1];   // [4096,4096]
    const float* Bm   = (const float*)d_in[2];   // [4096,40]
    const float* bias = (const float*)d_in[3];   // [1,4096]
    const int*   idx  = (const int*)  d_in[4];   // [40]
    float* out = (float*)d_out;
    (void)in_sizes; (void)n_in; (void)out_size;

    init_kernel<<<1, 1024>>>(idx);
    absmax_wconv_kernel<<<AM_BLOCKS + WC_BLOCKS, 256>>>((const float4*)x,
                                                        M_ROWS * K_IN / 4, W, Bm);
    quant_kernel<<<2048, 256>>>((const float4*)x);

    cudaFuncSetAttribute(gemm_kernel, cudaFuncAttributeMaxDynamicSharedMemorySize, SMEM_BYTES);
    dim3 grid(N_OUT / BN, M_ROWS / BM);   // n fastest: CTAs sharing an A strip co-run
    gemm_kernel<<<grid, NTHREADS, SMEM_BYTES>>>(bias, out);
}